// round 13
// baseline (speedup 1.0000x reference)
#include <cuda_runtime.h>
#include <cuda_bf16.h>
#include <cstdint>
#include <math.h>

// Problem constants (fixed shapes)
#define BB 4
#define SS 12
#define NN 4096
#define CC 64
#define HH 128
#define BS (BB*SS)              // 48
#define JTOT (BS*HH)            // 6144
#define OUT_ELEMS (BS*NN*HH)    // 25165824
#define A_ELEMS (NN*NN)         // 16777216

// Scratch (device globals)
__device__ __align__(16) float g_d[NN];
__device__ __align__(16) float g_xemb[OUT_ELEMS];               // fp32 [bs][n][h]
__device__ __align__(16) __nv_bfloat16 g_Abf[A_ELEMS];          // bf16 A
__device__ __align__(16) __nv_bfloat16 g_zT[(size_t)JTOT*NN];   // bf16 Z^T [j=bs*128+h][k]

// ---------------------------------------------------------------------------
// PTX helpers (sm_103 virtual-target legal)
// ---------------------------------------------------------------------------
__device__ __forceinline__ void cpasync16(uint32_t saddr, const void* gaddr) {
    asm volatile("cp.async.cg.shared.global [%0], [%1], 16;" :: "r"(saddr), "l"(gaddr));
}
#define CP_COMMIT() asm volatile("cp.async.commit_group;" ::: "memory")
#define CP_WAIT(n)  asm volatile("cp.async.wait_group %0;" :: "n"(n) : "memory")

#define LDSM_X4(r0,r1,r2,r3,addr) \
    asm volatile("ldmatrix.sync.aligned.m8n8.x4.shared.b16 {%0,%1,%2,%3}, [%4];" \
        : "=r"(r0), "=r"(r1), "=r"(r2), "=r"(r3) : "r"(addr))

#define MMA16816(d, a0,a1,a2,a3, b0,b1) \
    asm volatile("mma.sync.aligned.m16n8k16.row.col.f32.bf16.bf16.f32 " \
        "{%0,%1,%2,%3}, {%4,%5,%6,%7}, {%8,%9}, {%0,%1,%2,%3};" \
        : "+f"((d)[0]), "+f"((d)[1]), "+f"((d)[2]), "+f"((d)[3]) \
        : "r"(a0), "r"(a1), "r"(a2), "r"(a3), "r"(b0), "r"(b1))

// ---------------------------------------------------------------------------
// Kernel 1 (fused): per row of A: rowsum -> d[i], and A fp32 -> bf16
// One block per row, 256 threads, 4 float4 per thread.
// ---------------------------------------------------------------------------
__global__ __launch_bounds__(256) void rowconv_kernel(const float* __restrict__ A) {
    int row = blockIdx.x;
    const float4* Arow = (const float4*)(A + (size_t)row * NN);
    uint2* Brow = (uint2*)(g_Abf + (size_t)row * NN);
    float s = 0.f;
    #pragma unroll
    for (int u = 0; u < 4; u++) {
        int idx = threadIdx.x + u * 256;
        float4 v = Arow[idx];
        s += v.x + v.y + v.z + v.w;
        alignas(8) __nv_bfloat16 b[4] = {
            __float2bfloat16(v.x), __float2bfloat16(v.y),
            __float2bfloat16(v.z), __float2bfloat16(v.w) };
        Brow[idx] = *(const uint2*)b;
    }
    __shared__ float red[8];
    #pragma unroll
    for (int o = 16; o > 0; o >>= 1) s += __shfl_down_sync(0xffffffffu, s, o);
    if ((threadIdx.x & 31) == 0) red[threadIdx.x >> 5] = s;
    __syncthreads();
    if (threadIdx.x < 8) {
        float t = red[threadIdx.x];
        #pragma unroll
        for (int o = 4; o > 0; o >>= 1) t += __shfl_down_sync(0xffu, t, o);
        if (threadIdx.x == 0) g_d[row] = rsqrtf(t + 1.0f);
    }
}

// ---------------------------------------------------------------------------
// Kernel 2: x_emb fp32 AND Z^T bf16 (Z^T[j][k] = d[k]*x_emb[bs,k,h], j=bs*128+h)
// W row cached in registers; xs reads are warp-broadcast LDS.
// ---------------------------------------------------------------------------
#define EMB_ROWS 8
__global__ __launch_bounds__(128) void emb_kernel(const float* __restrict__ x,
                                                  const float* __restrict__ W) {
    __shared__ float Ws[HH * CC];
    __shared__ float xs[EMB_ROWS][CC];
    int t = threadIdx.x;
    for (int i = t; i < HH * CC; i += 128) Ws[i] = W[i];
    size_t row0 = (size_t)blockIdx.x * EMB_ROWS;
    const float* xb = x + row0 * CC;
    for (int i = t; i < EMB_ROWS * CC; i += 128) xs[i / CC][i % CC] = xb[i];
    __syncthreads();

    float wreg[CC];
    #pragma unroll
    for (int c = 0; c < CC; c++) wreg[c] = Ws[t * CC + c];

    float vals[EMB_ROWS];
    #pragma unroll
    for (int r = 0; r < EMB_ROWS; r++) {
        float s = 0.f;
        #pragma unroll
        for (int c = 0; c < CC; c++) s += xs[r][c] * wreg[c];
        vals[r] = s;
        g_xemb[(row0 + r) * HH + t] = s;
    }
    int bs  = (int)(row0 >> 12);       // row0 / 4096
    int rib = (int)(row0 & 4095);      // k index within slice
    alignas(16) __nv_bfloat16 zb[8];
    #pragma unroll
    for (int r = 0; r < EMB_ROWS; r++)
        zb[r] = __float2bfloat16(g_d[rib + r] * vals[r]);
    *(uint4*)&g_zT[((size_t)(bs * HH + t)) * NN + rib] = *(const uint4*)zb;
}

// ---------------------------------------------------------------------------
// Kernel 3: HMMA GEMM  D = A_bf @ Z^T_bf  (CTA 128x128, 4 warps of 64x64),
//           fused epilogue out = sigmoid(x_emb - d[i]*D)
// ---------------------------------------------------------------------------
#define PITCH 144
#define TILEB (128 * PITCH)        // 18432
#define G_STAGE (2 * TILEB)        // 36864 (A tile + B tile)
#define G_SMEM (2 * G_STAGE + 512)

__global__ void __launch_bounds__(128, 2) gemm_mma(float* __restrict__ out) {
    extern __shared__ char smem[];
    const uint32_t sb = (uint32_t)__cvta_generic_to_shared(smem);
    float* sD = (float*)(smem + 2 * G_STAGE);
    const int tid = threadIdx.x;
    const int wid = tid >> 5, lid = tid & 31;
    const int warp_m = wid & 1, warp_n = wid >> 1;   // 2x2 warps of 64x64
    const int bs = blockIdx.x;                        // col tile == one (b,s) slice
    const int i0 = blockIdx.y * 128;

    if (tid < 128) sD[tid] = g_d[i0 + tid];

    const __nv_bfloat16* Ag = g_Abf + (size_t)i0 * NN;
    const __nv_bfloat16* Bg = g_zT + (size_t)bs * HH * NN;

    auto load_stage = [&](int st, int k0) {
        uint32_t aB = sb + st * G_STAGE;
        uint32_t bB = aB + TILEB;
        #pragma unroll
        for (int u = 0; u < 8; u++) {
            int c = tid + u * 128;
            int row = c >> 3, kb = c & 7;
            cpasync16(aB + row * PITCH + kb * 16, Ag + (size_t)row * NN + k0 + kb * 8);
            cpasync16(bB + row * PITCH + kb * 16, Bg + (size_t)row * NN + k0 + kb * 8);
        }
        CP_COMMIT();
    };

    float acc[4][8][4];
    #pragma unroll
    for (int mb = 0; mb < 4; mb++)
        #pragma unroll
        for (int nb = 0; nb < 8; nb++)
            #pragma unroll
            for (int q = 0; q < 4; q++) acc[mb][nb][q] = 0.f;

    const int o = lid >> 3, r = lid & 7;
    const int amPart = warp_m * 64 + (o & 1) * 8 + r;
    const int akPart = (o >> 1) * 8;
    const int bnPart = warp_n * 64 + (o >> 1) * 8 + r;
    const int bkPart = (o & 1) * 8;

    load_stage(0, 0);

    for (int i = 0; i < NN / 64; i++) {
        if (i + 1 < NN / 64) { load_stage((i + 1) & 1, (i + 1) * 64); CP_WAIT(1); }
        else                 { CP_WAIT(0); }
        __syncthreads();

        const uint32_t aT = sb + (i & 1) * G_STAGE;
        const uint32_t bT = aT + TILEB;

        #pragma unroll
        for (int kk = 0; kk < 4; kk++) {
            uint32_t a[4][4], b[4][4];
            #pragma unroll
            for (int mb = 0; mb < 4; mb++) {
                uint32_t addr = aT + (amPart + mb * 16) * PITCH + (kk * 16 + akPart) * 2;
                LDSM_X4(a[mb][0], a[mb][1], a[mb][2], a[mb][3], addr);
            }
            #pragma unroll
            for (int nb = 0; nb < 4; nb++) {
                uint32_t addr = bT + (bnPart + nb * 16) * PITCH + (kk * 16 + bkPart) * 2;
                LDSM_X4(b[nb][0], b[nb][1], b[nb][2], b[nb][3], addr);
            }
            #pragma unroll
            for (int mb = 0; mb < 4; mb++)
                #pragma unroll
                for (int n8 = 0; n8 < 8; n8++) {
                    const uint32_t* bp = &b[n8 >> 1][(n8 & 1) * 2];
                    MMA16816(acc[mb][n8], a[mb][0], a[mb][1], a[mb][2], a[mb][3],
                             bp[0], bp[1]);
                }
        }
        __syncthreads();
    }

    // --- fused epilogue: out = sigmoid(x_emb - d[i]*acc) ---
    const float* xeB = g_xemb + (size_t)bs * NN * HH;
    float* outB = out + (size_t)bs * NN * HH;
    const int rq = lid >> 2, cq = (lid & 3) * 2;
    #pragma unroll
    for (int mb = 0; mb < 4; mb++) {
        #pragma unroll
        for (int half = 0; half < 2; half++) {
            int rloc = warp_m * 64 + mb * 16 + rq + half * 8;
            int iG = i0 + rloc;
            float di = sD[rloc];
            const float* xe = xeB + (size_t)iG * HH;
            float* op = outB + (size_t)iG * HH;
            #pragma unroll
            for (int n8 = 0; n8 < 8; n8++) {
                int h = warp_n * 64 + n8 * 8 + cq;
                float2 xv = *(const float2*)(xe + h);
                float v0 = xv.x - di * acc[mb][n8][half * 2 + 0];
                float v1 = xv.y - di * acc[mb][n8][half * 2 + 1];
                float2 ov;
                ov.x = 1.0f / (1.0f + __expf(-v0));
                ov.y = 1.0f / (1.0f + __expf(-v1));
                *(float2*)(op + h) = ov;
            }
        }
    }
}

// ---------------------------------------------------------------------------
// Kernel 4: pass-through copy of A into tail of d_out
// ---------------------------------------------------------------------------
__global__ void copyA_kernel(const float* __restrict__ A, float* __restrict__ dst) {
    size_t i = (size_t)blockIdx.x * blockDim.x + threadIdx.x;
    ((float4*)dst)[i] = ((const float4*)A)[i];
}

// ---------------------------------------------------------------------------
extern "C" void kernel_launch(void* const* d_in, const int* in_sizes, int n_in,
                              void* d_out, int out_size) {
    const float* x = (const float*)d_in[0];
    const float* A = (const float*)d_in[1];
    const float* W = (const float*)d_in[2];
    float* out = (float*)d_out;

    cudaFuncSetAttribute(gemm_mma, cudaFuncAttributeMaxDynamicSharedMemorySize, G_SMEM);

    rowconv_kernel<<<NN, 256>>>(A);
    emb_kernel<<<(BS * NN) / EMB_ROWS, 128>>>(x, W);

    gemm_mma<<<dim3(BS, NN / 128), 128, G_SMEM>>>(out);

    if (out_size >= OUT_ELEMS + A_ELEMS) {
        copyA_kernel<<<(A_ELEMS / 4) / 256, 256>>>(A, out + OUT_ELEMS);
    }
}

// round 14
// speedup vs baseline: 1.6215x; 1.6215x over previous
#include <cuda_runtime.h>
#include <cuda_bf16.h>
#include <cstdint>
#include <math.h>

// Problem constants (fixed shapes)
#define BB 4
#define SS 12
#define NN 4096
#define CC 64
#define HH 128
#define BS (BB*SS)              // 48
#define JTOT (BS*HH)            // 6144
#define OUT_ELEMS (BS*NN*HH)    // 25165824
#define A_ELEMS (NN*NN)         // 16777216

// Scratch (device globals)
__device__ __align__(16) float g_d[NN];
__device__ __align__(16) float g_xemb[OUT_ELEMS];               // fp32 [bs][n][h]
__device__ __align__(16) __nv_bfloat16 g_Abf[A_ELEMS];          // bf16 A
__device__ __align__(16) __nv_bfloat16 g_zT[(size_t)JTOT*NN];   // bf16 Z^T [j=bs*128+h][k]

// ---------------------------------------------------------------------------
// PTX helpers (sm_103 virtual-target legal)
// ---------------------------------------------------------------------------
__device__ __forceinline__ void cpasync16(uint32_t saddr, const void* gaddr) {
    asm volatile("cp.async.cg.shared.global [%0], [%1], 16;" :: "r"(saddr), "l"(gaddr));
}
#define CP_COMMIT() asm volatile("cp.async.commit_group;" ::: "memory")
#define CP_WAIT(n)  asm volatile("cp.async.wait_group %0;" :: "n"(n) : "memory")

#define LDSM_X4(r0,r1,r2,r3,addr) \
    asm volatile("ldmatrix.sync.aligned.m8n8.x4.shared.b16 {%0,%1,%2,%3}, [%4];" \
        : "=r"(r0), "=r"(r1), "=r"(r2), "=r"(r3) : "r"(addr))

#define MMA16816(d, a0,a1,a2,a3, b0,b1) \
    asm volatile("mma.sync.aligned.m16n8k16.row.col.f32.bf16.bf16.f32 " \
        "{%0,%1,%2,%3}, {%4,%5,%6,%7}, {%8,%9}, {%0,%1,%2,%3};" \
        : "+f"((d)[0]), "+f"((d)[1]), "+f"((d)[2]), "+f"((d)[3]) \
        : "r"(a0), "r"(a1), "r"(a2), "r"(a3), "r"(b0), "r"(b1))

// ---------------------------------------------------------------------------
// Kernel 1 (fused): per row of A: rowsum -> d[i], and A fp32 -> bf16
// ---------------------------------------------------------------------------
__global__ __launch_bounds__(256) void rowconv_kernel(const float* __restrict__ A) {
    int row = blockIdx.x;
    const float4* Arow = (const float4*)(A + (size_t)row * NN);
    uint2* Brow = (uint2*)(g_Abf + (size_t)row * NN);
    float s = 0.f;
    #pragma unroll
    for (int u = 0; u < 4; u++) {
        int idx = threadIdx.x + u * 256;
        float4 v = Arow[idx];
        s += v.x + v.y + v.z + v.w;
        alignas(8) __nv_bfloat16 b[4] = {
            __float2bfloat16(v.x), __float2bfloat16(v.y),
            __float2bfloat16(v.z), __float2bfloat16(v.w) };
        Brow[idx] = *(const uint2*)b;
    }
    __shared__ float red[8];
    #pragma unroll
    for (int o = 16; o > 0; o >>= 1) s += __shfl_down_sync(0xffffffffu, s, o);
    if ((threadIdx.x & 31) == 0) red[threadIdx.x >> 5] = s;
    __syncthreads();
    if (threadIdx.x < 8) {
        float t = red[threadIdx.x];
        #pragma unroll
        for (int o = 4; o > 0; o >>= 1) t += __shfl_down_sync(0xffu, t, o);
        if (threadIdx.x == 0) g_d[row] = rsqrtf(t + 1.0f);
    }
}

// ---------------------------------------------------------------------------
// Kernel 2: x_emb fp32 AND Z^T bf16 (Z^T[j][k] = d[k]*x_emb[bs,k,h], j=bs*128+h)
// ---------------------------------------------------------------------------
#define EMB_ROWS 8
__global__ __launch_bounds__(128) void emb_kernel(const float* __restrict__ x,
                                                  const float* __restrict__ W) {
    __shared__ float Ws[HH * CC];
    __shared__ float xs[EMB_ROWS][CC];
    int t = threadIdx.x;
    for (int i = t; i < HH * CC; i += 128) Ws[i] = W[i];
    size_t row0 = (size_t)blockIdx.x * EMB_ROWS;
    const float* xb = x + row0 * CC;
    for (int i = t; i < EMB_ROWS * CC; i += 128) xs[i / CC][i % CC] = xb[i];
    __syncthreads();

    float wreg[CC];
    #pragma unroll
    for (int c = 0; c < CC; c++) wreg[c] = Ws[t * CC + c];

    float vals[EMB_ROWS];
    #pragma unroll
    for (int r = 0; r < EMB_ROWS; r++) {
        float s = 0.f;
        #pragma unroll
        for (int c = 0; c < CC; c++) s += xs[r][c] * wreg[c];
        vals[r] = s;
        g_xemb[(row0 + r) * HH + t] = s;
    }
    int bs  = (int)(row0 >> 12);
    int rib = (int)(row0 & 4095);
    alignas(16) __nv_bfloat16 zb[8];
    #pragma unroll
    for (int r = 0; r < EMB_ROWS; r++)
        zb[r] = __float2bfloat16(g_d[rib + r] * vals[r]);
    *(uint4*)&g_zT[((size_t)(bs * HH + t)) * NN + rib] = *(const uint4*)zb;
}

// ---------------------------------------------------------------------------
// Kernel 3: HMMA GEMM  D = A_bf @ Z^T_bf  (CTA 128x128, 8 warps of 32x64),
//           3-stage cp.async pipeline, K-chunk 32.
//           Fused epilogue: out = sigmoid(x_emb - d[i]*D)
// ---------------------------------------------------------------------------
#define KCH 32
#define NCHUNK (NN / KCH)          // 128
#define PITCH 80                    // 32 bf16 = 64B data + 16B skew
#define TILEB (128 * PITCH)         // 10240
#define G_STAGE (2 * TILEB)         // 20480 (A tile + B tile)
#define G_SMEM (3 * G_STAGE + 512)  // 61952

__global__ void __launch_bounds__(256, 2) gemm_mma(float* __restrict__ out) {
    extern __shared__ char smem[];
    const uint32_t sb = (uint32_t)__cvta_generic_to_shared(smem);
    float* sD = (float*)(smem + 3 * G_STAGE);
    const int tid = threadIdx.x;
    const int wid = tid >> 5, lid = tid & 31;
    const int warp_m = wid & 3, warp_n = wid >> 2;   // 4x2 warps of 32x64
    const int bs = blockIdx.x;                        // col tile == one (b,s) slice
    const int i0 = blockIdx.y * 128;

    if (tid < 128) sD[tid] = g_d[i0 + tid];

    const __nv_bfloat16* Ag = g_Abf + (size_t)i0 * NN;
    const __nv_bfloat16* Bg = g_zT + (size_t)bs * HH * NN;

    // per stage: each operand 128 rows x 4 x 16B = 512 transfers; 2/thread/operand
    auto load_stage = [&](int st, int k0) {
        uint32_t aB = sb + st * G_STAGE;
        uint32_t bB = aB + TILEB;
        #pragma unroll
        for (int u = 0; u < 2; u++) {
            int c = tid + u * 256;
            int row = c >> 2, kb = c & 3;
            cpasync16(aB + row * PITCH + kb * 16, Ag + (size_t)row * NN + k0 + kb * 8);
            cpasync16(bB + row * PITCH + kb * 16, Bg + (size_t)row * NN + k0 + kb * 8);
        }
        CP_COMMIT();
    };

    float acc[2][8][4];
    #pragma unroll
    for (int mb = 0; mb < 2; mb++)
        #pragma unroll
        for (int nb = 0; nb < 8; nb++)
            #pragma unroll
            for (int q = 0; q < 4; q++) acc[mb][nb][q] = 0.f;

    const int o = lid >> 3, r = lid & 7;
    const int amPart = warp_m * 32 + (o & 1) * 8 + r;
    const int akPart = (o >> 1) * 8;
    const int bnPart = warp_n * 64 + (o >> 1) * 8 + r;
    const int bkPart = (o & 1) * 8;

    load_stage(0, 0);
    load_stage(1, KCH);

    int st = 0;
    for (int i = 0; i < NCHUNK; i++) {
        if (i + 1 < NCHUNK) { CP_WAIT(1); } else { CP_WAIT(0); }
        __syncthreads();
        if (i + 2 < NCHUNK) load_stage((st + 2) % 3, (i + 2) * KCH);

        const uint32_t aT = sb + st * G_STAGE;
        const uint32_t bT = aT + TILEB;

        #pragma unroll
        for (int kk = 0; kk < 2; kk++) {
            uint32_t a[2][4], b[4][4];
            #pragma unroll
            for (int mb = 0; mb < 2; mb++) {
                uint32_t addr = aT + (amPart + mb * 16) * PITCH + (kk * 16 + akPart) * 2;
                LDSM_X4(a[mb][0], a[mb][1], a[mb][2], a[mb][3], addr);
            }
            #pragma unroll
            for (int nb = 0; nb < 4; nb++) {
                uint32_t addr = bT + (bnPart + nb * 16) * PITCH + (kk * 16 + bkPart) * 2;
                LDSM_X4(b[nb][0], b[nb][1], b[nb][2], b[nb][3], addr);
            }
            #pragma unroll
            for (int mb = 0; mb < 2; mb++)
                #pragma unroll
                for (int n8 = 0; n8 < 8; n8++) {
                    const uint32_t* bp = &b[n8 >> 1][(n8 & 1) * 2];
                    MMA16816(acc[mb][n8], a[mb][0], a[mb][1], a[mb][2], a[mb][3],
                             bp[0], bp[1]);
                }
        }
        st = (st + 1) % 3;
        __syncthreads();
    }

    // --- fused epilogue: out = sigmoid(x_emb - d[i]*acc) ---
    const float* xeB = g_xemb + (size_t)bs * NN * HH;
    float* outB = out + (size_t)bs * NN * HH;
    const int rq = lid >> 2, cq = (lid & 3) * 2;
    #pragma unroll
    for (int mb = 0; mb < 2; mb++) {
        #pragma unroll
        for (int half = 0; half < 2; half++) {
            int rloc = warp_m * 32 + mb * 16 + rq + half * 8;
            int iG = i0 + rloc;
            float di = sD[rloc];
            const float* xe = xeB + (size_t)iG * HH;
            float* op = outB + (size_t)iG * HH;
            #pragma unroll
            for (int n8 = 0; n8 < 8; n8++) {
                int h = warp_n * 64 + n8 * 8 + cq;
                float2 xv = *(const float2*)(xe + h);
                float v0 = xv.x - di * acc[mb][n8][half * 2 + 0];
                float v1 = xv.y - di * acc[mb][n8][half * 2 + 1];
                float2 ov;
                ov.x = 1.0f / (1.0f + __expf(-v0));
                ov.y = 1.0f / (1.0f + __expf(-v1));
                *(float2*)(op + h) = ov;
            }
        }
    }
}

// ---------------------------------------------------------------------------
// Kernel 4: pass-through copy of A into tail of d_out
// ---------------------------------------------------------------------------
__global__ void copyA_kernel(const float* __restrict__ A, float* __restrict__ dst) {
    size_t i = (size_t)blockIdx.x * blockDim.x + threadIdx.x;
    ((float4*)dst)[i] = ((const float4*)A)[i];
}

// ---------------------------------------------------------------------------
extern "C" void kernel_launch(void* const* d_in, const int* in_sizes, int n_in,
                              void* d_out, int out_size) {
    const float* x = (const float*)d_in[0];
    const float* A = (const float*)d_in[1];
    const float* W = (const float*)d_in[2];
    float* out = (float*)d_out;

    cudaFuncSetAttribute(gemm_mma, cudaFuncAttributeMaxDynamicSharedMemorySize, G_SMEM);

    rowconv_kernel<<<NN, 256>>>(A);
    emb_kernel<<<(BS * NN) / EMB_ROWS, 128>>>(x, W);

    gemm_mma<<<dim3(BS, NN / 128), 256, G_SMEM>>>(out);

    if (out_size >= OUT_ELEMS + A_ELEMS) {
        copyA_kernel<<<(A_ELEMS / 4) / 256, 256>>>(A, out + OUT_ELEMS);
    }
}

// round 15
// speedup vs baseline: 1.7655x; 1.0888x over previous
#include <cuda_runtime.h>
#include <cuda_bf16.h>
#include <cstdint>
#include <math.h>

// Problem constants (fixed shapes)
#define BB 4
#define SS 12
#define NN 4096
#define CC 64
#define HH 128
#define BS (BB*SS)              // 48
#define JTOT (BS*HH)            // 6144
#define OUT_ELEMS (BS*NN*HH)    // 25165824
#define A_ELEMS (NN*NN)         // 16777216

// Scratch (device globals)
__device__ __align__(16) float g_d[NN];
__device__ __align__(16) float g_xemb[OUT_ELEMS];               // fp32 [bs][n][h]
__device__ __align__(16) __nv_bfloat16 g_Abf[A_ELEMS];          // bf16 A
__device__ __align__(16) __nv_bfloat16 g_zT[(size_t)JTOT*NN];   // bf16 Z^T [j=bs*128+h][k]

// ---------------------------------------------------------------------------
// PTX helpers (sm_103 virtual-target legal)
// ---------------------------------------------------------------------------
__device__ __forceinline__ void cpasync16(uint32_t saddr, const void* gaddr) {
    asm volatile("cp.async.cg.shared.global [%0], [%1], 16;" :: "r"(saddr), "l"(gaddr));
}
#define CP_COMMIT() asm volatile("cp.async.commit_group;" ::: "memory")
#define CP_WAIT(n)  asm volatile("cp.async.wait_group %0;" :: "n"(n) : "memory")

#define LDSM_X4(r0,r1,r2,r3,addr) \
    asm volatile("ldmatrix.sync.aligned.m8n8.x4.shared.b16 {%0,%1,%2,%3}, [%4];" \
        : "=r"(r0), "=r"(r1), "=r"(r2), "=r"(r3) : "r"(addr))

#define MMA16816(d, a0,a1,a2,a3, b0,b1) \
    asm volatile("mma.sync.aligned.m16n8k16.row.col.f32.bf16.bf16.f32 " \
        "{%0,%1,%2,%3}, {%4,%5,%6,%7}, {%8,%9}, {%0,%1,%2,%3};" \
        : "+f"((d)[0]), "+f"((d)[1]), "+f"((d)[2]), "+f"((d)[3]) \
        : "r"(a0), "r"(a1), "r"(a2), "r"(a3), "r"(b0), "r"(b1))

// ---------------------------------------------------------------------------
// Kernel 1 (fused): per row of A: rowsum -> d[i], A fp32 -> bf16,
//                   AND fp32 A pass-through copy into d_out tail.
// One block per row, 256 threads, 4 float4 per thread.
// ---------------------------------------------------------------------------
__global__ __launch_bounds__(256) void rowconv_kernel(const float* __restrict__ A,
                                                      float* __restrict__ Atail) {
    int row = blockIdx.x;
    const float4* Arow = (const float4*)(A + (size_t)row * NN);
    uint2* Brow = (uint2*)(g_Abf + (size_t)row * NN);
    float4* Crow = (float4*)(Atail + (size_t)row * NN);
    float s = 0.f;
    #pragma unroll
    for (int u = 0; u < 4; u++) {
        int idx = threadIdx.x + u * 256;
        float4 v = Arow[idx];
        s += v.x + v.y + v.z + v.w;
        alignas(8) __nv_bfloat16 b[4] = {
            __float2bfloat16(v.x), __float2bfloat16(v.y),
            __float2bfloat16(v.z), __float2bfloat16(v.w) };
        Brow[idx] = *(const uint2*)b;
        Crow[idx] = v;
    }
    __shared__ float red[8];
    #pragma unroll
    for (int o = 16; o > 0; o >>= 1) s += __shfl_down_sync(0xffffffffu, s, o);
    if ((threadIdx.x & 31) == 0) red[threadIdx.x >> 5] = s;
    __syncthreads();
    if (threadIdx.x < 8) {
        float t = red[threadIdx.x];
        #pragma unroll
        for (int o = 4; o > 0; o >>= 1) t += __shfl_down_sync(0xffu, t, o);
        if (threadIdx.x == 0) g_d[row] = rsqrtf(t + 1.0f);
    }
}

// ---------------------------------------------------------------------------
// Kernel 2: x_emb fp32 AND Z^T bf16 (Z^T[j][k] = d[k]*x_emb[bs,k,h], j=bs*128+h)
// ---------------------------------------------------------------------------
#define EMB_ROWS 8
__global__ __launch_bounds__(128) void emb_kernel(const float* __restrict__ x,
                                                  const float* __restrict__ W) {
    __shared__ float Ws[HH * CC];
    __shared__ float xs[EMB_ROWS][CC];
    int t = threadIdx.x;
    for (int i = t; i < HH * CC; i += 128) Ws[i] = W[i];
    size_t row0 = (size_t)blockIdx.x * EMB_ROWS;
    const float* xb = x + row0 * CC;
    for (int i = t; i < EMB_ROWS * CC; i += 128) xs[i / CC][i % CC] = xb[i];
    __syncthreads();

    float wreg[CC];
    #pragma unroll
    for (int c = 0; c < CC; c++) wreg[c] = Ws[t * CC + c];

    float vals[EMB_ROWS];
    #pragma unroll
    for (int r = 0; r < EMB_ROWS; r++) {
        float s = 0.f;
        #pragma unroll
        for (int c = 0; c < CC; c++) s += xs[r][c] * wreg[c];
        vals[r] = s;
        g_xemb[(row0 + r) * HH + t] = s;
    }
    int bs  = (int)(row0 >> 12);
    int rib = (int)(row0 & 4095);
    alignas(16) __nv_bfloat16 zb[8];
    #pragma unroll
    for (int r = 0; r < EMB_ROWS; r++)
        zb[r] = __float2bfloat16(g_d[rib + r] * vals[r]);
    *(uint4*)&g_zT[((size_t)(bs * HH + t)) * NN + rib] = *(const uint4*)zb;
}

// ---------------------------------------------------------------------------
// Kernel 3: HMMA GEMM  D = A_bf @ Z^T_bf  (R7-proven config:
//           CTA 128x128, 8 warps of 32x64, K-chunk 64, 2-stage cp.async),
//           fused epilogue out = sigmoid(x_emb - d[i]*D)
// ---------------------------------------------------------------------------
#define KCH 64
#define NCHUNK (NN / KCH)        // 64
#define PITCH 144                 // 64 bf16 = 128B data + 16B skew
#define TILE_BYTES (128 * PITCH)  // 18432
#define STAGE_BYTES (2 * TILE_BYTES)
#define SM_D_OFF (2 * STAGE_BYTES)          // 73728
#define SMEM_TOT (SM_D_OFF + 128 * 4)       // 74240

__global__ void __launch_bounds__(256, 2) gemm_mma(float* __restrict__ out) {
    extern __shared__ char smem[];
    const uint32_t sb = (uint32_t)__cvta_generic_to_shared(smem);
    const int tid = threadIdx.x;
    const int wid = tid >> 5, lid = tid & 31;
    const int warp_m = wid & 3, warp_n = wid >> 2;   // 4 x 2 warp grid
    const int bs = blockIdx.x;                        // N-tile == one (b,s) slice
    const int i0 = blockIdx.y * 128;                  // row tile base

    float* sD = (float*)(smem + SM_D_OFF);
    if (tid < 128) sD[tid] = g_d[i0 + tid];

    const __nv_bfloat16* Ag = g_Abf + (size_t)i0 * NN;
    const __nv_bfloat16* Bg = g_zT + (size_t)bs * HH * NN;

    auto load_stage = [&](int stage, int k0) {
        uint32_t aBase = sb + stage * STAGE_BYTES;
        uint32_t bBase = aBase + TILE_BYTES;
        #pragma unroll
        for (int u = 0; u < 4; u++) {
            int c = tid + u * 256;
            int row = c >> 3, kb = c & 7;
            cpasync16(aBase + row * PITCH + kb * 16, Ag + (size_t)row * NN + k0 + kb * 8);
            cpasync16(bBase + row * PITCH + kb * 16, Bg + (size_t)row * NN + k0 + kb * 8);
        }
        CP_COMMIT();
    };

    float acc[2][8][4];
    #pragma unroll
    for (int mb = 0; mb < 2; mb++)
        #pragma unroll
        for (int nb = 0; nb < 8; nb++)
            #pragma unroll
            for (int q = 0; q < 4; q++) acc[mb][nb][q] = 0.f;

    const int o = lid >> 3, r = lid & 7;
    const int amPart = warp_m * 32 + (o & 1) * 8 + r;
    const int akPart = (o >> 1) * 8;
    const int bnPart = warp_n * 64 + (o >> 1) * 8 + r;
    const int bkPart = (o & 1) * 8;

    load_stage(0, 0);

    for (int i = 0; i < NCHUNK; i++) {
        if (i + 1 < NCHUNK) load_stage((i + 1) & 1, (i + 1) * KCH);
        if (i + 1 < NCHUNK) { CP_WAIT(1); } else { CP_WAIT(0); }
        __syncthreads();

        const uint32_t aT = sb + (i & 1) * STAGE_BYTES;
        const uint32_t bT = aT + TILE_BYTES;

        #pragma unroll
        for (int kk = 0; kk < 4; kk++) {
            uint32_t a[2][4];
            #pragma unroll
            for (int mb = 0; mb < 2; mb++) {
                uint32_t addr = aT + (amPart + mb * 16) * PITCH + (kk * 16 + akPart) * 2;
                LDSM_X4(a[mb][0], a[mb][1], a[mb][2], a[mb][3], addr);
            }
            uint32_t b[4][4];
            #pragma unroll
            for (int nb = 0; nb < 4; nb++) {
                uint32_t addr = bT + (bnPart + nb * 16) * PITCH + (kk * 16 + bkPart) * 2;
                LDSM_X4(b[nb][0], b[nb][1], b[nb][2], b[nb][3], addr);
            }
            #pragma unroll
            for (int mb = 0; mb < 2; mb++)
                #pragma unroll
                for (int n8 = 0; n8 < 8; n8++) {
                    const uint32_t* bp = &b[n8 >> 1][(n8 & 1) * 2];
                    MMA16816(acc[mb][n8], a[mb][0], a[mb][1], a[mb][2], a[mb][3],
                             bp[0], bp[1]);
                }
        }
        __syncthreads();
    }

    // --- fused epilogue: out = sigmoid(x_emb - d[i]*acc) ---
    const float* xeB = g_xemb + (size_t)bs * NN * HH;
    float* outB = out + (size_t)bs * NN * HH;
    const int rq = lid >> 2, cq = (lid & 3) * 2;
    #pragma unroll
    for (int mb = 0; mb < 2; mb++) {
        #pragma unroll
        for (int half = 0; half < 2; half++) {
            int rloc = warp_m * 32 + mb * 16 + rq + half * 8;
            int iG = i0 + rloc;
            float di = sD[rloc];
            const float* xe = xeB + (size_t)iG * HH;
            float* op = outB + (size_t)iG * HH;
            #pragma unroll
            for (int n8 = 0; n8 < 8; n8++) {
                int h = warp_n * 64 + n8 * 8 + cq;
                float2 xv = *(const float2*)(xe + h);
                float v0 = xv.x - di * acc[mb][n8][half * 2 + 0];
                float v1 = xv.y - di * acc[mb][n8][half * 2 + 1];
                float2 ov;
                ov.x = 1.0f / (1.0f + __expf(-v0));
                ov.y = 1.0f / (1.0f + __expf(-v1));
                *(float2*)(op + h) = ov;
            }
        }
    }
}

// ---------------------------------------------------------------------------
// Fallback A-copy (only if out tail not present in rowconv path)
// ---------------------------------------------------------------------------
__global__ void copyA_kernel(const float* __restrict__ A, float* __restrict__ dst) {
    size_t i = (size_t)blockIdx.x * blockDim.x + threadIdx.x;
    ((float4*)dst)[i] = ((const float4*)A)[i];
}

// Scratch sink for rowconv's A-copy when out tail is absent
__device__ __align__(16) float g_sinkA[NN];   // unused row-sink (never read)

// ---------------------------------------------------------------------------
extern "C" void kernel_launch(void* const* d_in, const int* in_sizes, int n_in,
                              void* d_out, int out_size) {
    const float* x = (const float*)d_in[0];
    const float* A = (const float*)d_in[1];
    const float* W = (const float*)d_in[2];
    float* out = (float*)d_out;

    cudaFuncSetAttribute(gemm_mma, cudaFuncAttributeMaxDynamicSharedMemorySize, SMEM_TOT);

    bool hasTail = (out_size >= OUT_ELEMS + A_ELEMS);
    if (hasTail) {
        rowconv_kernel<<<NN, 256>>>(A, out + OUT_ELEMS);
    } else {
        // no tail in output: still need d + bf16 A; reuse kernel writing copy
        // into g_xemb scratch (overwritten later by emb? no - emb writes all of
        // g_xemb) -> safe sink: write into g_zT region then emb overwrites it.
        rowconv_kernel<<<NN, 256>>>(A, (float*)g_zT);
    }
    emb_kernel<<<(BS * NN) / EMB_ROWS, 128>>>(x, W);

    gemm_mma<<<dim3(BS, NN / 128), 256, SMEM_TOT>>>(out);
}